// round 9
// baseline (speedup 1.0000x reference)
#include <cuda_runtime.h>

#define TT 64
#define FULL 0xffffffffu

__host__ __device__ constexpr int popc4(int k) {
    return (k & 1) + ((k >> 1) & 1) + ((k >> 2) & 1) + ((k >> 3) & 1);
}
// k(sub,u) for layout sub=(bit3,bit0), u=(bit2,bit1); Finv basis {1,2,4,8}->{3,6,12,11}
__host__ __device__ constexpr int kof(int sub_, int u_) {
    return ((sub_ & 1) ? 3 : 0) ^ ((u_ & 1) ? 6 : 0) ^ ((u_ & 2) ? 12 : 0) ^ ((sub_ & 2) ? 11 : 0);
}

__device__ __forceinline__ float sx(float v, int m) { return __shfl_xor_sync(FULL, v, m); }
__device__ __forceinline__ float tanhap(float v) {
    float r;
    asm("tanh.approx.f32 %0, %1;" : "=f"(r) : "f"(v));
    return r;
}

struct QState { float cc0, cc1, h0, h1; };

// One QLSTM step for one batch element (R7 algebra, unchanged).
__device__ __forceinline__ void qstep(
    QState& s, float4 xq,
    const float hw0[4], const float C[4],
    const float Wh2[4][2], const float Wo[2][4], const float bo[2],
    const float sg3[4], const float sg3p[4], const float t0[4],
    const float b1s[4], const float b2s[4],
    bool f01, bool f3, float A1c, float A2c, int b16, int sub)
{
    const float xk[4] = {xq.x + hw0[0], xq.y + hw0[1], xq.z + hw0[2], xq.w + hw0[3]};

    // S1: angle all-reduce (one stage) + local sincos (4 wires)
    float pw[4];
#pragma unroll
    for (int w = 0; w < 4; ++w)
        pw[w] = fmaf(s.h0, Wh2[w][0], s.h1 * Wh2[w][1]);
    float cw[4], swv[4];
#pragma unroll
    for (int w = 0; w < 4; ++w) {
        float p1 = sx(pw[w], 1), p2 = sx(pw[w], 2), p3 = sx(pw[w], 3);
        float ang = ((pw[w] + p1) + (p2 + p3)) + xk[w];
        __sincosf(ang, &swv[w], &cw[w]);
    }

    const float ec0 = f01 ? swv[0] : cw[0];
    const float ec1 = f01 ? swv[1] : cw[1], es1 = f01 ? cw[1] : swv[1];
    const float c2  = cw[2], s2 = swv[2];
    const float ec3 = f3 ? swv[3] : cw[3],  es3 = f3 ? cw[3] : swv[3];

    // product build
    const float a01c = ec0 * ec1, a01s = ec0 * es1;
    const float m2c = c2 * ec3, m2s = s2 * ec3;
    const float m3s = s2 * es3, m3c = c2 * es3;
    float r0 = a01c * m2c;
    float r1 = a01s * m2s;
    float r2 = a01c * m3s;
    float r3 = a01s * m3c;

    // S2: single exchange stage -> wire3 + wire0 local
    float rm1[4], rm2[4], rm3[4];
    rm1[0] = sx(r0, 1); rm1[1] = sx(r1, 1); rm1[2] = sx(r2, 1); rm1[3] = sx(r3, 1);
    rm2[0] = sx(r0, 2); rm2[1] = sx(r1, 2); rm2[2] = sx(r2, 2); rm2[3] = sx(r3, 2);
    rm3[0] = sx(r0, 3); rm3[1] = sx(r1, 3); rm3[2] = sx(r2, 3); rm3[3] = sx(r3, 3);
    const float rr[4] = {r0, r1, r2, r3};
    float Re[4], Im[4];
#pragma unroll
    for (int u = 0; u < 4; ++u) {
        float w3  = fmaf(C[3], rr[u],  sg3[u]  * rm2[u]);
        float w3p = fmaf(C[3], rm1[u], sg3p[u] * rm3[u]);
        Re[u] = C[0] * w3;
        Im[u] = t0[u] * w3p;
    }
    // RX wire1 (local): pairs (0,1),(2,3)
#pragma unroll
    for (int u = 0; u < 4; u += 2) {
        const int v = u | 1;
        float ar = Re[u], ai = Im[u], br = Re[v], bi = Im[v];
        Re[u] = fmaf(b1s[u], bi, C[1] * ar); Im[u] = fmaf(-b1s[u], br, C[1] * ai);
        Re[v] = fmaf(b1s[v], ai, C[1] * br); Im[v] = fmaf(-b1s[v], ar, C[1] * bi);
    }
    // RX wire2 (local): pairs (0,2),(1,3)
#pragma unroll
    for (int u = 0; u < 2; ++u) {
        const int v = u | 2;
        float ar = Re[u], ai = Im[u], br = Re[v], bi = Im[v];
        Re[u] = fmaf(b2s[u], bi, C[2] * ar); Im[u] = fmaf(-b2s[u], br, C[2] * ai);
        Re[v] = fmaf(b2s[v], ai, C[2] * br); Im[v] = fmaf(-b2s[v], ar, C[2] * bi);
    }

    // probabilities + per-lane Walsh patterns
    float q0 = fmaf(Re[0], Re[0], Im[0] * Im[0]);
    float q1 = fmaf(Re[1], Re[1], Im[1] * Im[1]);
    float q2 = fmaf(Re[2], Re[2], Im[2] * Im[2]);
    float q3 = fmaf(Re[3], Re[3], Im[3] * Im[3]);
    float PA = (q0 - q1) - (q2 - q3);
    float PB = (q0 - q1) + (q2 - q3);

    // S3: Walsh cross-sub reduce (one stage)
    float A1 = sx(PA, 1), A2 = sx(PA, 2), A3 = sx(PA, 3);
    float B1 = sx(PB, 1), B2 = sx(PB, 2), B3 = sx(PB, 3);
    float ex0 = (PA + A1) - (A2 + A3);
    float ex1 = (PB - B1) + (B2 - B3);
    float tA  = PA - A1, tB = A2 - A3;
    float ex2 = tA + tB;
    float ex3 = tA - tB;

    // activations for own 2 comps
    float ga0 = fmaf(ex1, Wo[0][1], fmaf(ex0, Wo[0][0], bo[0]));
    float gb0 = fmaf(ex3, Wo[0][3], ex2 * Wo[0][2]);
    float ga1 = fmaf(ex1, Wo[1][1], fmaf(ex0, Wo[1][0], bo[1]));
    float gb1 = fmaf(ex3, Wo[1][3], ex2 * Wo[1][2]);
    float act0 = fmaf(A1c, tanhap(ga0 + gb0), A2c);
    float act1 = fmaf(A1c, tanhap(ga1 + gb1), A2c);

    // S4: gather f,i,u,o; cell update
    const int s0 = b16 + sub;
    float fv0 = __shfl_sync(FULL, act0, s0);
    float fv1 = __shfl_sync(FULL, act1, s0);
    float iv0 = __shfl_sync(FULL, act0, s0 + 4);
    float iv1 = __shfl_sync(FULL, act1, s0 + 4);
    float uv0 = __shfl_sync(FULL, act0, s0 + 8);
    float uv1 = __shfl_sync(FULL, act1, s0 + 8);
    float ov0 = __shfl_sync(FULL, act0, s0 + 12);
    float ov1 = __shfl_sync(FULL, act1, s0 + 12);

    s.cc0 = fmaf(fv0, s.cc0, iv0 * uv0);
    s.cc1 = fmaf(fv1, s.cc1, iv1 * uv1);
    s.h0 = ov0 * tanhap(s.cc0);
    s.h1 = ov1 * tanhap(s.cc1);
}

__global__ void __launch_bounds__(64, 1)
qlstm2x(const float* __restrict__ x,
        const float* __restrict__ w_in,  const float* __restrict__ b_in,
        const float* __restrict__ w_out, const float* __restrict__ b_out,
        const float* __restrict__ wq_f,  const float* __restrict__ wq_i,
        const float* __restrict__ wq_u,  const float* __restrict__ wq_o,
        const float* __restrict__ w_fc,  const float* __restrict__ b_fc,
        float* __restrict__ out, int B)
{
    const int lane = threadIdx.x & 31;
    const int gl   = threadIdx.x & 15;
    const int g    = gl >> 2;          // gate (f,i,u,o)
    const int sub  = gl & 3;           // slot bits (3,0)
    const int b16  = lane & ~15;
    const int lg   = threadIdx.x >> 4; // local group 0..3
    const int gg   = blockIdx.x * 4 + lg;

    int eA = 2 * gg, eB = 2 * gg + 1;
    const bool okA = (eA < B), okB = (eB < B);
    if (eA >= B) eA = B - 1;
    if (eB >= B) eB = B - 1;

    // ------------- pre-pass: xproj for both elements -> shared -------------
    __shared__ float4 sxp[8][TT];
#pragma unroll
    for (int el = 0; el < 2; ++el) {
        const float* xe = x + (long)(el ? eB : eA) * TT * 32;
        float acc[4][4];
#pragma unroll
        for (int i = 0; i < 4; ++i)
#pragma unroll
            for (int w = 0; w < 4; ++w) acc[i][w] = 0.f;
#pragma unroll
        for (int c = 0; c < 8; ++c) {
            float4 wv[4];
#pragma unroll
            for (int w = 0; w < 4; ++w)
                wv[w] = *reinterpret_cast<const float4*>(&w_in[w * 40 + 8 + 4 * c]);
#pragma unroll
            for (int i = 0; i < 4; ++i) {
                float4 xv = *reinterpret_cast<const float4*>(&xe[(gl * 4 + i) * 32 + 4 * c]);
#pragma unroll
                for (int w = 0; w < 4; ++w) {
                    acc[i][w] = fmaf(xv.x, wv[w].x, acc[i][w]);
                    acc[i][w] = fmaf(xv.y, wv[w].y, acc[i][w]);
                    acc[i][w] = fmaf(xv.z, wv[w].z, acc[i][w]);
                    acc[i][w] = fmaf(xv.w, wv[w].w, acc[i][w]);
                }
            }
        }
#pragma unroll
        for (int i = 0; i < 4; ++i)
            sxp[2 * lg + el][gl * 4 + i] =
                make_float4(0.5f * acc[i][0], 0.5f * acc[i][1],
                            0.5f * acc[i][2], 0.5f * acc[i][3]);
    }
    __syncthreads();

    const float* wq = (g == 0) ? wq_f : (g == 1) ? wq_i : (g == 2) ? wq_u : wq_o;

    // ---- circuit constants (shared by both elements) ----
    float hw0[4], C[4], Sv[4];
#pragma unroll
    for (int w = 0; w < 4; ++w) {
        hw0[w] = 0.5f * (__ldg(&wq[w]) + __ldg(&b_in[w]));
        float a = 0.5f * __ldg(&wq[4 + w]);
        C[w] = cosf(a); Sv[w] = sinf(a);
    }
    float Wh2[4][2];
#pragma unroll
    for (int w = 0; w < 4; ++w)
#pragma unroll
        for (int j = 0; j < 2; ++j)
            Wh2[w][j] = 0.5f * __ldg(&w_in[w * 40 + 2 * sub + j]);

    const int sig0 = sub & 1, sig1 = (sub >> 1) & 1;
    const float chi0  = sig1 ? -1.f : 1.f;
    const float chi12 = sig0 ? -1.f : 1.f;
    const float chi3  = (sig0 ^ sig1) ? -1.f : 1.f;
    const float chi[4] = {chi0, chi12, chi12, chi3};
    const float asc = (g == 2) ? 1.f : 0.5f;
    const float A1c = (g == 2) ? 1.f : 0.5f;
    const float A2c = (g == 2) ? 0.f : 0.5f;
    float Wo[2][4], bo[2];
#pragma unroll
    for (int i = 0; i < 2; ++i) {
        bo[i] = asc * __ldg(&b_out[2 * sub + i]);
#pragma unroll
        for (int w = 0; w < 4; ++w)
            Wo[i][w] = asc * chi[w] * __ldg(&w_out[(2 * sub + i) * 4 + w]);
    }

    float sg3[4], sg3p[4], t0[4], b1s[4], b2s[4];
#pragma unroll
    for (int u = 0; u < 4; ++u) {
        const int k   = kof(sub, u);
        const int cls = popc4(k) & 3;
        sg3[u] = ((((popc4(k ^ 11) & 3) + 1 - cls) & 3) == 0) ?  Sv[3] : -Sv[3];
        const int kp   = kof(sub ^ 1, u);
        const int clsp = popc4(kp) & 3;
        sg3p[u] = ((((popc4(kp ^ 11) & 3) + 1 - clsp) & 3) == 0) ?  Sv[3] : -Sv[3];
        t0 [u] = ((((popc4(k ^ 3)  & 3) - cls) & 3) == 0) ? -Sv[0] :  Sv[0];
        b1s[u] = ((((popc4(k ^ 6)  & 3) - cls) & 3) == 0) ?  Sv[1] : -Sv[1];
        b2s[u] = ((((popc4(k ^ 12) & 3) - cls) & 3) == 0) ?  Sv[2] : -Sv[2];
    }
    const bool f01 = (sig0 ^ sig1) != 0;
    const bool f3  = sig1 != 0;

    QState sA = {0.f, 0.f, 0.f, 0.f};
    QState sB = {0.f, 0.f, 0.f, 0.f};

#pragma unroll 1
    for (int t = 0; t < TT; ++t) {
        float4 xqA = sxp[2 * lg][t];
        float4 xqB = sxp[2 * lg + 1][t];
        qstep(sA, xqA, hw0, C, Wh2, Wo, bo, sg3, sg3p, t0, b1s, b2s,
              f01, f3, A1c, A2c, b16, sub);
        qstep(sB, xqB, hw0, C, Wh2, Wo, bo, sg3, sg3p, t0, b1s, b2s,
              f01, f3, A1c, A2c, b16, sub);
    }

    // ---- final projections ----
    const float wf0 = __ldg(&w_fc[2 * sub]), wf1 = __ldg(&w_fc[2 * sub + 1]);
    const float bfc = __ldg(&b_fc[0]);
    float pA = fmaf(sA.h1, wf1, sA.h0 * wf0);
    float pB = fmaf(sB.h1, wf1, sB.h0 * wf0);
    pA += sx(pA, 1); pB += sx(pB, 1);
    pA += sx(pA, 2); pB += sx(pB, 2);
    if (gl == 0) {
        if (okA) out[eA] = pA + bfc;
        if (okB) out[eB] = pB + bfc;
    }
}

extern "C" void kernel_launch(void* const* d_in, const int* in_sizes, int n_in,
                              void* d_out, int out_size) {
    const float* x     = (const float*)d_in[0];
    const float* w_in  = (const float*)d_in[1];
    const float* b_in  = (const float*)d_in[2];
    const float* w_out = (const float*)d_in[3];
    const float* b_out = (const float*)d_in[4];
    const float* wq_f  = (const float*)d_in[5];
    const float* wq_i  = (const float*)d_in[6];
    const float* wq_u  = (const float*)d_in[7];
    const float* wq_o  = (const float*)d_in[8];
    const float* w_fc  = (const float*)d_in[9];
    const float* b_fc  = (const float*)d_in[10];

    int B = in_sizes[0] / (TT * 32);
    int groups = (B + 1) / 2;              // 2 elements per 16-lane group
    int blocks = (groups + 3) / 4;         // 4 groups per 64-thread block
    qlstm2x<<<blocks, 64>>>(x, w_in, b_in, w_out, b_out,
                            wq_f, wq_i, wq_u, wq_o, w_fc, b_fc,
                            (float*)d_out, B);
}

// round 10
// speedup vs baseline: 1.1617x; 1.1617x over previous
#include <cuda_runtime.h>

#define TT 64
#define FULL 0xffffffffu

__host__ __device__ constexpr int popc4(int k) {
    return (k & 1) + ((k >> 1) & 1) + ((k >> 2) & 1) + ((k >> 3) & 1);
}

__device__ __forceinline__ float sx(float v, int m) { return __shfl_xor_sync(FULL, v, m); }
__device__ __forceinline__ float tanhap(float v) {
    float r;
    asm("tanh.approx.f32 %0, %1;" : "=f"(r) : "f"(v));
    return r;
}
__device__ __forceinline__ float pick4(const float a[4], int j) {
    float x = (j & 2) ? a[2] : a[0];
    float y = (j & 2) ? a[3] : a[1];
    return (j & 1) ? y : x;
}

// One warp = one batch element. lane = g*8 + sub.
// slot bits: bit0=s0(lane0), bit3=s1(lane1), bit1=s2(lane2), bit2=u(local).
// k(sub,u) = Finv image: basis bit0->3, bit1->6, bit2->12, bit3->11.
__global__ void __launch_bounds__(128)
qlstm32(const float* __restrict__ x,
        const float* __restrict__ w_in,  const float* __restrict__ b_in,
        const float* __restrict__ w_out, const float* __restrict__ b_out,
        const float* __restrict__ wq_f,  const float* __restrict__ wq_i,
        const float* __restrict__ wq_u,  const float* __restrict__ wq_o,
        const float* __restrict__ w_fc,  const float* __restrict__ b_fc,
        float* __restrict__ out, int B)
{
    const int lane = threadIdx.x & 31;
    const int wib  = threadIdx.x >> 5;     // warp in block (0..3)
    int e = blockIdx.x * 4 + wib;
    const bool ok = (e < B);
    if (!ok) e = B - 1;

    const int g   = lane >> 3;             // gate (f,i,u,o)
    const int sub = lane & 7;              // sub-lane = h component index
    const int s0 = sub & 1, s1 = (sub >> 1) & 1, s2 = (sub >> 2) & 1;
    const int wown = sub & 3;              // own wire for sincos

    // ---------------- pre-pass: xproj -> shared (warp-private) ----------------
    __shared__ float4 sxp[4][TT];
    {
        const float* xe = x + (long)e * TT * 32;
        const int t0i = lane * 2;
        float acc[2][4];
#pragma unroll
        for (int i = 0; i < 2; ++i)
#pragma unroll
            for (int w = 0; w < 4; ++w) acc[i][w] = 0.f;
#pragma unroll
        for (int c = 0; c < 8; ++c) {
            float4 wv[4];
#pragma unroll
            for (int w = 0; w < 4; ++w)
                wv[w] = *reinterpret_cast<const float4*>(&w_in[w * 40 + 8 + 4 * c]);
            float4 xv0 = *reinterpret_cast<const float4*>(&xe[t0i * 32 + 4 * c]);
            float4 xv1 = *reinterpret_cast<const float4*>(&xe[(t0i + 1) * 32 + 4 * c]);
#pragma unroll
            for (int w = 0; w < 4; ++w) {
                acc[0][w] = fmaf(xv0.x, wv[w].x, acc[0][w]);
                acc[0][w] = fmaf(xv0.y, wv[w].y, acc[0][w]);
                acc[0][w] = fmaf(xv0.z, wv[w].z, acc[0][w]);
                acc[0][w] = fmaf(xv0.w, wv[w].w, acc[0][w]);
                acc[1][w] = fmaf(xv1.x, wv[w].x, acc[1][w]);
                acc[1][w] = fmaf(xv1.y, wv[w].y, acc[1][w]);
                acc[1][w] = fmaf(xv1.z, wv[w].z, acc[1][w]);
                acc[1][w] = fmaf(xv1.w, wv[w].w, acc[1][w]);
            }
        }
        sxp[wib][t0i]     = make_float4(0.5f * acc[0][0], 0.5f * acc[0][1],
                                        0.5f * acc[0][2], 0.5f * acc[0][3]);
        sxp[wib][t0i + 1] = make_float4(0.5f * acc[1][0], 0.5f * acc[1][1],
                                        0.5f * acc[1][2], 0.5f * acc[1][3]);
    }
    __syncwarp();

    const float* wq = (g == 0) ? wq_f : (g == 1) ? wq_i : (g == 2) ? wq_u : wq_o;

    // ---- circuit constants ----
    float hw0[4], C[4], Sv[4];
#pragma unroll
    for (int w = 0; w < 4; ++w) {
        hw0[w] = 0.5f * (__ldg(&wq[w]) + __ldg(&b_in[w]));
        float a = 0.5f * __ldg(&wq[4 + w]);
        C[w] = cosf(a); Sv[w] = sinf(a);
    }
    const float hw0own = pick4(hw0, wown);

    // h-projection weight of own comp for each wire (pre-scaled 0.5)
    float Whl[4];
#pragma unroll
    for (int w = 0; w < 4; ++w) Whl[w] = 0.5f * __ldg(&w_in[w * 40 + sub]);

    // output proj row for comp=sub; Walsh chars + activation prescale folded
    const float chiw[4] = {
        ((s1 ^ s2) ? -1.f : 1.f),        // wire0: (-1)^(s1+s2)
        ((s0 ^ s2) ? -1.f : 1.f),        // wire1: (-1)^(s0+s2)
        ((s0 ^ s2) ? -1.f : 1.f),        // wire2
        ((s0 ^ s1 ^ s2) ? -1.f : 1.f)    // wire3
    };
    const float asc = (g == 2) ? 1.f : 0.5f;
    const float A1c = (g == 2) ? 1.f : 0.5f;
    const float A2c = (g == 2) ? 0.f : 0.5f;
    float Wo[4];
#pragma unroll
    for (int w = 0; w < 4; ++w)
        Wo[w] = asc * chiw[w] * __ldg(&w_out[sub * 4 + w]);
    const float bo = asc * __ldg(&b_out[sub]);

    // ---- per-lane sign tables (u = local slot bit2) ----
    float sg3[2], sg3p[2], t0[2], b1s[2], b2s[2];
#pragma unroll
    for (int u = 0; u < 2; ++u) {
        const int k = (s0 ? 3 : 0) ^ (s2 ? 6 : 0) ^ (s1 ? 11 : 0) ^ (u ? 12 : 0);
        const int cls = popc4(k) & 3;
        sg3[u] = ((((popc4(k ^ 11) & 3) + 1 - cls) & 3) == 0) ?  Sv[3] : -Sv[3];
        const int kp = k ^ 3;
        const int clsp = popc4(kp) & 3;
        sg3p[u] = ((((popc4(kp ^ 11) & 3) + 1 - clsp) & 3) == 0) ?  Sv[3] : -Sv[3];
        t0 [u] = ((((popc4(k ^ 3)  & 3) - cls) & 3) == 0) ? -Sv[0] :  Sv[0];
        b1s[u] = ((((popc4(k ^ 6)  & 3) - cls) & 3) == 0) ?  Sv[1] : -Sv[1];
        b2s[u] = ((((popc4(k ^ 12) & 3) - cls) & 3) == 0) ?  Sv[2] : -Sv[2];
    }
    // product-factor swap bits (k bits at u=0)
    const bool kb0 = (s0 ^ s1) != 0;          // wire0 factor
    const bool kb1 = (s0 ^ s1 ^ s2) != 0;     // wire1 factor

    float cc = 0.f, h = 0.f;                  // own comp state

#pragma unroll 1
    for (int t = 0; t < TT; ++t) {
        float4 xq = sxp[wib][t];
        const float xarr[4] = {xq.x, xq.y, xq.z, xq.w};
        const float xo = pick4(xarr, wown) + hw0own;

        // ---- S1a: h-partials + one-stage XOR-transpose-reduce over 8 subs ----
        float pwv[4];
#pragma unroll
        for (int w = 0; w < 4; ++w) pwv[w] = h * Whl[w];
        float red = pick4(pwv, wown);
#pragma unroll
        for (int m = 1; m < 8; ++m)
            red += sx(pick4(pwv, (sub ^ m) & 3), m);
        const float ang = red + xo;

        // ---- S1b: own sincos; share all 4 wires ----
        float mys, myc;
        __sincosf(ang, &mys, &myc);
        const int b4 = lane & ~3;
        float cw[4], sw[4];
#pragma unroll
        for (int w = 0; w < 4; ++w) {
            cw[w] = __shfl_sync(FULL, myc, b4 | w);
            sw[w] = __shfl_sync(FULL, mys, b4 | w);
        }

        // ---- product build (2 slots per lane) ----
        const float ec0 = kb0 ? sw[0] : cw[0];
        const float ec1 = kb1 ? sw[1] : cw[1];
        const float T2a = s2 ? sw[2] : cw[2], T2b = s2 ? cw[2] : sw[2];
        const float T3a = s1 ? sw[3] : cw[3], T3b = s1 ? cw[3] : sw[3];
        const float e01 = ec0 * ec1;
        float r0 = e01 * (T2a * T3a);
        float r1 = e01 * (T2b * T3b);

        // ---- S2: fused wire3(mask2) + wire0(mask1) exchange ----
        float a1_0 = sx(r0, 1), a1_1 = sx(r1, 1);
        float a2_0 = sx(r0, 2), a2_1 = sx(r1, 2);
        float a3_0 = sx(r0, 3), a3_1 = sx(r1, 3);
        float w3_0  = fmaf(C[3], r0,   sg3[0]  * a2_0);
        float w3_1  = fmaf(C[3], r1,   sg3[1]  * a2_1);
        float w3p_0 = fmaf(C[3], a1_0, sg3p[0] * a3_0);
        float w3p_1 = fmaf(C[3], a1_1, sg3p[1] * a3_1);
        float Re0 = C[0] * w3_0,  Im0 = t0[0] * w3p_0;
        float Re1 = C[0] * w3_1,  Im1 = t0[1] * w3p_1;

        // ---- RX wire1: cross-lane (mask 4), complex ----
        float Rp0 = sx(Re0, 4), Ip0 = sx(Im0, 4);
        float Rp1 = sx(Re1, 4), Ip1 = sx(Im1, 4);
        Re0 = fmaf(b1s[0], Ip0, C[1] * Re0); Im0 = fmaf(-b1s[0], Rp0, C[1] * Im0);
        Re1 = fmaf(b1s[1], Ip1, C[1] * Re1); Im1 = fmaf(-b1s[1], Rp1, C[1] * Im1);

        // ---- RX wire2: local complex butterfly (slot pair) ----
        {
            float ar = Re0, ai = Im0, br = Re1, bi = Im1;
            Re0 = fmaf(b2s[0], bi, C[2] * ar); Im0 = fmaf(-b2s[0], br, C[2] * ai);
            Re1 = fmaf(b2s[1], ai, C[2] * br); Im1 = fmaf(-b2s[1], ar, C[2] * bi);
        }

        // ---- probabilities + local Walsh patterns ----
        float q0 = fmaf(Re0, Re0, Im0 * Im0);
        float q1 = fmaf(Re1, Re1, Im1 * Im1);
        float PA = q0 - q1;     // wires 0,2,3 (u-signed)
        float PB = q0 + q1;     // wire 1

        // ---- S3: one-stage all-to-all Walsh over 8 subs ----
        float PA1 = sx(PA, 1), PA2 = sx(PA, 2), PA3 = sx(PA, 3);
        float PA4 = sx(PA, 4), PA5 = sx(PA, 5), PA6 = sx(PA, 6), PA7 = sx(PA, 7);
        float PB1 = sx(PB, 1), PB2 = sx(PB, 2), PB3 = sx(PB, 3);
        float PB4 = sx(PB, 4), PB5 = sx(PB, 5), PB6 = sx(PB, 6), PB7 = sx(PB, 7);
        float t01p = PA + PA1,  t01m = PA - PA1;
        float t23p = PA2 + PA3, t23m = PA2 - PA3;
        float t45p = PA4 + PA5, t45m = PA4 - PA5;
        float t67p = PA6 + PA7, t67m = PA6 - PA7;
        float ex0 = (t01p - t23p) - (t45p - t67p);   // a=6
        float ex2 = (t01m + t23m) - (t45m + t67m);   // a=5
        float ex3 = (t01m - t23m) - (t45m - t67m);   // a=7
        float b01m = PB - PB1,  b23m = PB2 - PB3;
        float b45m = PB4 - PB5, b67m = PB6 - PB7;
        float ex1 = (b01m + b23m) - (b45m + b67m);   // a=5 on PB

        // ---- activation for own (gate, comp) ----
        float gv = fmaf(ex1, Wo[1], fmaf(ex0, Wo[0], bo));
        gv = fmaf(ex3, Wo[3], fmaf(ex2, Wo[2], gv));
        float act = fmaf(A1c, tanhap(gv), A2c);

        // ---- S4: gather 4 gates for own comp; cell update ----
        float fv = __shfl_sync(FULL, act, sub);
        float iv = __shfl_sync(FULL, act, sub + 8);
        float uv = __shfl_sync(FULL, act, sub + 16);
        float ov = __shfl_sync(FULL, act, sub + 24);
        cc = fmaf(fv, cc, iv * uv);
        h = ov * tanhap(cc);
    }

    // ---- final projection: sum over 8 comps (gate-0 lanes hold truth) ----
    float p = h * __ldg(&w_fc[sub]);
    p += sx(p, 1);
    p += sx(p, 2);
    p += sx(p, 4);
    if (lane == 0 && ok) out[e] = p + __ldg(&b_fc[0]);
}

extern "C" void kernel_launch(void* const* d_in, const int* in_sizes, int n_in,
                              void* d_out, int out_size) {
    const float* x     = (const float*)d_in[0];
    const float* w_in  = (const float*)d_in[1];
    const float* b_in  = (const float*)d_in[2];
    const float* w_out = (const float*)d_in[3];
    const float* b_out = (const float*)d_in[4];
    const float* wq_f  = (const float*)d_in[5];
    const float* wq_i  = (const float*)d_in[6];
    const float* wq_u  = (const float*)d_in[7];
    const float* wq_o  = (const float*)d_in[8];
    const float* w_fc  = (const float*)d_in[9];
    const float* b_fc  = (const float*)d_in[10];

    int B = in_sizes[0] / (TT * 32);
    int blocks = (B + 3) / 4;              // 4 elements (warps) per block
    qlstm32<<<blocks, 128>>>(x, w_in, b_in, w_out, b_out,
                             wq_f, wq_i, wq_u, wq_o, w_fc, b_fc,
                             (float*)d_out, B);
}